// round 11
// baseline (speedup 1.0000x reference)
#include <cstdint>
#include <cuda_runtime.h>
#include <cuda_bf16.h>
#include <mma.h>

using namespace nvcuda;

// Problem dims
#define B_   64
#define T_   1024
#define H_   512
#define M_   (B_ * T_)      // 65536 rows
#define L_   4
#define G3H  (3 * H_)       // 1536

// Weight pack offsets (elements)
#define OFF_WIN  0
#define OFF_WIH  (512*512)
#define OFF_WO1  (OFF_WIH + 4*1536*512)
#define OFF_WO2  (OFF_WO1 + 512*512)
#define WTOT     (OFF_WO2 + 512*512)

// ---------------- static device scratch (no runtime allocation) ----------------
__device__ float          g_gi[(size_t)M_ * G3H];       // 402 MB
__device__ __nv_bfloat16  g_aAh[(size_t)M_ * H_];       // activation pair buffer A
__device__ __nv_bfloat16  g_aAl[(size_t)M_ * H_];
__device__ __nv_bfloat16  g_aBh[(size_t)M_ * H_];       // activation pair buffer B
__device__ __nv_bfloat16  g_aBl[(size_t)M_ * H_];
__device__ __nv_bfloat16  g_wh[WTOT];                   // pre-split weights
__device__ __nv_bfloat16  g_wl[WTOT];
__device__ unsigned int   g_hb2[2 * B_ * H_];           // packed (hi,lo) hidden state, double buffered
__device__ int            g_bar[4 * 32];                // per-group barrier counters (128B apart)

// ---------------- helpers ----------------
__device__ __forceinline__ void split_bf16(float v, __nv_bfloat16& hi, __nv_bfloat16& lo) {
    hi = __float2bfloat16(v);
    lo = __float2bfloat16(v - __bfloat162float(hi));
}
__device__ __forceinline__ float fast_sigmoid(float x) {
    return __fdividef(1.0f, 1.0f + __expf(-x));
}
__device__ __forceinline__ float fast_tanh(float x) {
    float e = __expf(-2.0f * x);
    return __fdividef(1.0f - e, 1.0f + e);
}
__device__ __forceinline__ void cp_async16(void* dst, const void* src) {
    uint32_t d = (uint32_t)__cvta_generic_to_shared(dst);
    asm volatile("cp.async.cg.shared.global [%0], [%1], 16;" :: "r"(d), "l"(src));
}
__device__ __forceinline__ void cp_commit() { asm volatile("cp.async.commit_group;"); }
__device__ __forceinline__ void cp_wait0()  { asm volatile("cp.async.wait_group 0;"); }
__device__ __forceinline__ void cp_wait1()  { asm volatile("cp.async.wait_group 1;"); }

// =================================================================================
// split_all: ONE kernel that pre-splits x and all weights into bf16 hi/lo pairs
// =================================================================================
#define Q0 (M_ * H_ / 4)
#define Q1 (512 * 512 / 4)
#define Q2 (4 * G3H * H_ / 4)
#define QTOT (Q0 + Q1 + Q2 + Q1 + Q1)

__global__ __launch_bounds__(256)
void split_all(const float* __restrict__ x,   const float* __restrict__ w_in,
               const float* __restrict__ w_ih, const float* __restrict__ w_o1,
               const float* __restrict__ w_o2)
{
    long i = (long)blockIdx.x * 256 + threadIdx.x;
    if (i >= QTOT) return;
    const float* src; __nv_bfloat16 *dh, *dl; long off;
    if (i < Q0)                { src = x;    dh = g_aAh;          dl = g_aAl;          off = i; }
    else if (i < Q0 + Q1)      { src = w_in; dh = g_wh + OFF_WIN; dl = g_wl + OFF_WIN; off = i - Q0; }
    else if (i < Q0 + Q1 + Q2) { src = w_ih; dh = g_wh + OFF_WIH; dl = g_wl + OFF_WIH; off = i - Q0 - Q1; }
    else if (i < Q0 + Q1 + Q2 + Q1) { src = w_o1; dh = g_wh + OFF_WO1; dl = g_wl + OFF_WO1; off = i - Q0 - Q1 - Q2; }
    else                       { src = w_o2; dh = g_wh + OFF_WO2; dl = g_wl + OFF_WO2; off = i - Q0 - Q1 - Q2 - Q1; }

    float4 v = ((const float4*)src)[off];
    __nv_bfloat16 h0,l0,h1,l1,h2,l2,h3,l3;
    split_bf16(v.x, h0, l0); split_bf16(v.y, h1, l1);
    split_bf16(v.z, h2, l2); split_bf16(v.w, h3, l3);
    ((__nv_bfloat162*)dh)[2*off]   = __nv_bfloat162(h0, h1);
    ((__nv_bfloat162*)dh)[2*off+1] = __nv_bfloat162(h2, h3);
    ((__nv_bfloat162*)dl)[2*off]   = __nv_bfloat162(l0, l1);
    ((__nv_bfloat162*)dl)[2*off+1] = __nv_bfloat162(l2, l3);
}

// =================================================================================
// hbinit: zero hidden-state buffer 0 and barrier counters (replaces memsets)
// =================================================================================
__global__ __launch_bounds__(256)
void hbinit_kernel()
{
    int i = blockIdx.x * 256 + threadIdx.x;
    if (i < (B_ * H_ * 4) / 16)        // buffer 0: 64*512 uint = 131072 B -> 8192 uint4
        ((uint4*)g_hb2)[i] = make_uint4(0, 0, 0, 0);
    if (blockIdx.x == 0 && threadIdx.x < 4 * 32)
        g_bar[threadIdx.x] = 0;
}

// =================================================================================
// GEMM v2 (unchanged from R10): pre-split pairs, cp.async double-buffered
// =================================================================================
#define BM 128
#define BN 128
#define BK 32
#define GLD 40
#define TILE (128 * GLD)
#define GEMM_SMEM (2 * 4 * TILE * 2)   // 81,920 B

template<int RELU, int OUTPAIR>
__global__ __launch_bounds__(256, 2)
void gemm2(const __nv_bfloat16* __restrict__ Ah, const __nv_bfloat16* __restrict__ Al,
           const __nv_bfloat16* __restrict__ Wh, const __nv_bfloat16* __restrict__ Wl,
           const float* __restrict__ bias,
           float* __restrict__ Cf,
           __nv_bfloat16* __restrict__ Ch, __nv_bfloat16* __restrict__ Cl,
           int M, int N, int K)
{
    extern __shared__ __nv_bfloat16 sm[];

    const int tid  = threadIdx.x;
    const int m0   = blockIdx.y * BM;
    const int n0   = blockIdx.x * BN;
    const int w    = tid >> 5;
    const int lane = tid & 31;
    const int wm   = w >> 2;
    const int wn   = w & 3;

    wmma::fragment<wmma::accumulator, 16, 16, 16, float> acc[4][2];
    #pragma unroll
    for (int i = 0; i < 4; i++)
        #pragma unroll
        for (int j = 0; j < 2; j++)
            wmma::fill_fragment(acc[i][j], 0.0f);

    auto load_stage = [&](int s, int k0) {
        #pragma unroll
        for (int i = 0; i < 8; i++) {
            int cid  = tid + i * 256;
            int which = cid >> 9;
            int rem  = cid & 511;
            int row  = rem >> 2;
            int c8   = (rem & 3) * 8;
            const __nv_bfloat16* src;
            if      (which == 0) src = Ah + (size_t)(m0 + row) * K + k0 + c8;
            else if (which == 1) src = Al + (size_t)(m0 + row) * K + k0 + c8;
            else if (which == 2) src = Wh + (size_t)(n0 + row) * K + k0 + c8;
            else                 src = Wl + (size_t)(n0 + row) * K + k0 + c8;
            cp_async16(sm + (s * 4 + which) * TILE + row * GLD + c8, src);
        }
    };

    load_stage(0, 0);
    cp_commit();

    const int NKT = K / BK;
    for (int kt = 0; kt < NKT; kt++) {
        if (kt + 1 < NKT) {
            load_stage((kt + 1) & 1, (kt + 1) * BK);
            cp_commit();
            cp_wait1();
        } else {
            cp_wait0();
        }
        __syncthreads();

        const __nv_bfloat16* pAh = sm + ((kt & 1) * 4 + 0) * TILE;
        const __nv_bfloat16* pAl = sm + ((kt & 1) * 4 + 1) * TILE;
        const __nv_bfloat16* pWh = sm + ((kt & 1) * 4 + 2) * TILE;
        const __nv_bfloat16* pWl = sm + ((kt & 1) * 4 + 3) * TILE;

        #pragma unroll
        for (int kk = 0; kk < BK; kk += 16) {
            wmma::fragment<wmma::matrix_b, 16, 16, 16, __nv_bfloat16, wmma::col_major> bh[2], bl[2];
            #pragma unroll
            for (int nf = 0; nf < 2; nf++) {
                wmma::load_matrix_sync(bh[nf], pWh + (wn * 32 + nf * 16) * GLD + kk, GLD);
                wmma::load_matrix_sync(bl[nf], pWl + (wn * 32 + nf * 16) * GLD + kk, GLD);
            }
            #pragma unroll
            for (int mf = 0; mf < 4; mf++) {
                wmma::fragment<wmma::matrix_a, 16, 16, 16, __nv_bfloat16, wmma::row_major> ah, al;
                wmma::load_matrix_sync(ah, pAh + (wm * 64 + mf * 16) * GLD + kk, GLD);
                wmma::load_matrix_sync(al, pAl + (wm * 64 + mf * 16) * GLD + kk, GLD);
                #pragma unroll
                for (int nf = 0; nf < 2; nf++) {
                    wmma::mma_sync(acc[mf][nf], ah, bh[nf], acc[mf][nf]);
                    wmma::mma_sync(acc[mf][nf], ah, bl[nf], acc[mf][nf]);
                    wmma::mma_sync(acc[mf][nf], al, bh[nf], acc[mf][nf]);
                }
            }
        }
        __syncthreads();
    }

    float* scr   = (float*)sm;
    float* myscr = scr + w * 320;
    #pragma unroll
    for (int mf = 0; mf < 4; mf++) {
        #pragma unroll
        for (int nf = 0; nf < 2; nf++) {
            wmma::store_matrix_sync(myscr, acc[mf][nf], 20, wmma::mem_row_major);
            __syncwarp();
            #pragma unroll
            for (int e = 0; e < 8; e++) {
                int idx = e * 32 + lane;
                int r = idx >> 4, c = idx & 15;
                int row = m0 + wm * 64 + mf * 16 + r;
                int col = n0 + wn * 32 + nf * 16 + c;
                float v = myscr[r * 20 + c] + __ldg(&bias[col]);
                if (RELU) v = fmaxf(v, 0.0f);
                if (OUTPAIR) {
                    __nv_bfloat16 hi, lo; split_bf16(v, hi, lo);
                    Ch[(size_t)row * N + col] = hi;
                    Cl[(size_t)row * N + col] = lo;
                } else {
                    Cf[(size_t)row * N + col] = v;
                }
            }
            __syncwarp();
        }
    }
}

// =================================================================================
// Persistent GRU scan v4:
//  - h exchanged as ONE packed (hi,lo) bf162 array; __byte_perm unpack in staging
//  - batched __ldcg staging (no cp.async wait on critical path)
//  - relaxed-poll spin + single trailing acquire load
//  - register-resident weight fragments; 2-deep gi prefetch
// =================================================================================
#define SW        520
#define NBLK      32
#define GROUPS    4
#define BG        16
#define NTHR      384
#define SCAN_SMEM 50048

typedef wmma::fragment<wmma::matrix_b, 16, 16, 16, __nv_bfloat16, wmma::col_major> bfrag_t;
typedef wmma::fragment<wmma::matrix_a, 16, 16, 16, __nv_bfloat16, wmma::row_major> afrag_t;

__global__ __launch_bounds__(NTHR)
void scan_kernel(const float* __restrict__ gi, const float* __restrict__ whh,
                 const float* __restrict__ bhh,
                 __nv_bfloat16* __restrict__ ysh, __nv_bfloat16* __restrict__ ysl)
{
    extern __shared__ char smem_raw[];
    __nv_bfloat16* wtmp = (__nv_bfloat16*)smem_raw;        // init alias: 48 x SW
    __nv_bfloat16* hh = (__nv_bfloat16*)smem_raw;          // steady: 16 x SW
    __nv_bfloat16* hl = hh + 16 * SW;                      // 16 x SW
    float* gh  = (float*)(hl + 16 * SW);                   // [4][16][48]
    float* sbh = gh + 4 * 768;                             // 48

    const int tid   = threadIdx.x;
    const int g     = blockIdx.x >> 5;
    const int blk   = blockIdx.x & 31;
    const int c0    = blk * 16;
    const int w     = tid >> 5;
    const int ntile = w % 3;
    const int kq    = w / 3;
    const int bbase = g * BG;
    int* bar = &g_bar[g * 32];

    // ---- init: weight fragments into registers (hi pass, lo pass) ----
    bfrag_t bhf[8], blf[8];
    for (int i = tid; i < 48 * H_; i += NTHR) {
        int rl = i >> 9, k = i & 511;
        int grow = (rl >> 4) * H_ + c0 + (rl & 15);
        wtmp[rl * SW + k] = __float2bfloat16(whh[(size_t)grow * H_ + k]);
    }
    __syncthreads();
    #pragma unroll
    for (int i = 0; i < 8; i++)
        wmma::load_matrix_sync(bhf[i], wtmp + ntile * 16 * SW + kq * 128 + i * 16, SW);
    __syncthreads();
    for (int i = tid; i < 48 * H_; i += NTHR) {
        int rl = i >> 9, k = i & 511;
        int grow = (rl >> 4) * H_ + c0 + (rl & 15);
        float v = whh[(size_t)grow * H_ + k];
        wtmp[rl * SW + k] = __float2bfloat16(v - __bfloat162float(__float2bfloat16(v)));
    }
    __syncthreads();
    #pragma unroll
    for (int i = 0; i < 8; i++)
        wmma::load_matrix_sync(blf[i], wtmp + ntile * 16 * SW + kq * 128 + i * 16, SW);
    __syncthreads();
    if (tid < 48)
        sbh[tid] = bhh[(tid >> 4) * H_ + c0 + (tid & 15)];
    __syncthreads();

    // gi prefetch, 2 deep
    float a_r = 0.f, a_z = 0.f, a_n = 0.f, b_r = 0.f, b_z = 0.f, b_n = 0.f;
    const float* gbase = gi + (size_t)(bbase + (tid >> 4)) * T_ * G3H + (c0 + (tid & 15));
    if (tid < 256) {
        a_r = __ldg(gbase);            a_z = __ldg(gbase + H_);            a_n = __ldg(gbase + 2 * H_);
        b_r = __ldg(gbase + G3H);      b_z = __ldg(gbase + G3H + H_);      b_n = __ldg(gbase + G3H + 2 * H_);
    }

    for (int t = 0; t < T_; t++) {
        const int cur = t & 1, nxt = cur ^ 1;
        const unsigned int* src2 = g_hb2 + cur * (B_ * H_);

        // Stage packed h [16 x 512 x 4B] -> split smem (512 uint4 chunks, ~1.3/thread)
        // chunk = 4 elements; per row: 128 chunks
        for (int i = tid; i < 2048; i += NTHR) {
            int row = i >> 7;            // 0..15
            int c4  = (i & 127) * 4;     // element col
            uint4 v = __ldcg((const uint4*)(src2 + (size_t)(bbase + row) * H_ + c4));
            unsigned int h01 = __byte_perm(v.x, v.y, 0x5410);
            unsigned int l01 = __byte_perm(v.x, v.y, 0x7632);
            unsigned int h23 = __byte_perm(v.z, v.w, 0x5410);
            unsigned int l23 = __byte_perm(v.z, v.w, 0x7632);
            *(uint2*)&hh[row * SW + c4] = make_uint2(h01, h23);
            *(uint2*)&hl[row * SW + c4] = make_uint2(l01, l23);
        }
        __syncthreads();

        // gh partial[kq][16 x 48]: register-resident weights
        {
            wmma::fragment<wmma::accumulator, 16, 16, 16, float> acc;
            wmma::fill_fragment(acc, 0.0f);
            const int kbase = kq * 128;
            afrag_t ah, al;
            #pragma unroll
            for (int i = 0; i < 8; i++) {
                int k = kbase + i * 16;
                wmma::load_matrix_sync(ah, hh + k, SW);
                wmma::load_matrix_sync(al, hl + k, SW);
                wmma::mma_sync(acc, ah, bhf[i], acc);
                wmma::mma_sync(acc, ah, blf[i], acc);
                wmma::mma_sync(acc, al, bhf[i], acc);
            }
            wmma::store_matrix_sync(gh + kq * 768 + ntile * 16, acc, 48, wmma::mem_row_major);
        }
        __syncthreads();

        // Gate epilogue: 256 elements
        if (tid < 256) {
            int b = tid >> 4, j = tid & 15;
            int c = c0 + j;
            size_t rowoff = (size_t)(bbase + b) * T_ + t;
            int o = b * 48 + j;
            float gr = gh[o]      + gh[768 + o]      + gh[1536 + o]      + gh[2304 + o]      + sbh[j];
            float gz = gh[o + 16] + gh[768 + o + 16] + gh[1536 + o + 16] + gh[2304 + o + 16] + sbh[16 + j];
            float gn = gh[o + 32] + gh[768 + o + 32] + gh[1536 + o + 32] + gh[2304 + o + 32] + sbh[32 + j];
            float ho = __bfloat162float(hh[b * SW + c]) + __bfloat162float(hl[b * SW + c]);
            float r = fast_sigmoid(a_r + gr);
            float z = fast_sigmoid(a_z + gz);
            float n = fast_tanh(a_n + r * gn);
            float hn = (1.0f - z) * n + z * ho;
            __nv_bfloat16 hi, lo; split_bf16(hn, hi, lo);
            ysh[rowoff * H_ + c] = hi;
            ysl[rowoff * H_ + c] = lo;
            unsigned int packed = ((unsigned int)__bfloat16_as_ushort(hi)) |
                                  ((unsigned int)__bfloat16_as_ushort(lo) << 16);
            __stcg(&g_hb2[(size_t)nxt * (B_ * H_) + (size_t)(bbase + b) * H_ + c], packed);
        }

        // rotate prefetch: a <- b, issue t+2 into b
        if (tid < 256) {
            a_r = b_r; a_z = b_z; a_n = b_n;
            if (t + 2 < T_) {
                const float* gp = gbase + (size_t)(t + 2) * G3H;
                b_r = __ldg(gp);
                b_z = __ldg(gp + H_);
                b_n = __ldg(gp + 2 * H_);
            }
        }

        __syncthreads();   // order h' stores before release
        if (tid == 0) {
            asm volatile("red.release.gpu.global.add.s32 [%0], 1;" :: "l"(bar) : "memory");
            const int target = NBLK * (t + 1);
            int v;
            do {
                asm volatile("ld.relaxed.gpu.global.s32 %0, [%1];" : "=r"(v) : "l"(bar));
            } while (v < target);
            asm volatile("ld.acquire.gpu.global.s32 %0, [%1];" : "=r"(v) : "l"(bar));
        }
        __syncthreads();
    }
}

// =================================================================================
// Orchestration — launch order puts scan_kernel at position 5 (1-based) so the
// fixed ncu window (-s 5 -c 1) finally captures it.
// =================================================================================
extern "C" void kernel_launch(void* const* d_in, const int* in_sizes, int n_in,
                              void* d_out, int out_size)
{
    const float* x    = (const float*)d_in[0];
    const float* w_in = (const float*)d_in[1];
    const float* b_in = (const float*)d_in[2];
    const float* w_ih = (const float*)d_in[3];
    const float* w_hh = (const float*)d_in[4];
    const float* b_ih = (const float*)d_in[5];
    const float* b_hh = (const float*)d_in[6];
    const float* w_o1 = (const float*)d_in[7];
    const float* b_o1 = (const float*)d_in[8];
    const float* w_o2 = (const float*)d_in[9];
    const float* b_o2 = (const float*)d_in[10];
    float* out = (float*)d_out;
    (void)in_sizes; (void)n_in; (void)out_size;

    float *gi; __nv_bfloat16 *aAh, *aAl, *aBh, *aBl, *wh, *wl;
    cudaGetSymbolAddress((void**)&gi,  g_gi);
    cudaGetSymbolAddress((void**)&aAh, g_aAh);
    cudaGetSymbolAddress((void**)&aAl, g_aAl);
    cudaGetSymbolAddress((void**)&aBh, g_aBh);
    cudaGetSymbolAddress((void**)&aBl, g_aBl);
    cudaGetSymbolAddress((void**)&wh,  g_wh);
    cudaGetSymbolAddress((void**)&wl,  g_wl);

    cudaFuncSetAttribute(scan_kernel, cudaFuncAttributeMaxDynamicSharedMemorySize, SCAN_SMEM);
    cudaFuncSetAttribute(gemm2<1,1>, cudaFuncAttributeMaxDynamicSharedMemorySize, GEMM_SMEM);
    cudaFuncSetAttribute(gemm2<0,0>, cudaFuncAttributeMaxDynamicSharedMemorySize, GEMM_SMEM);

    // 1: all splits in one launch
    split_all<<<(QTOT + 255) / 256, 256>>>(x, w_in, w_ih, w_o1, w_o2);

    // 2: input Linear + ReLU -> pair B
    gemm2<1,1><<<dim3(H_ / BN, M_ / BM), 256, GEMM_SMEM>>>(
        aAh, aAl, wh + OFF_WIN, wl + OFF_WIN, b_in, nullptr, aBh, aBl, M_, H_, H_);

    __nv_bfloat16 *curh = aBh, *curl = aBl, *oth = aAh, *otl = aAl;
    for (int l = 0; l < L_; l++) {
        // 3 (+3 per layer): gi GEMM
        gemm2<0,0><<<dim3(G3H / BN, M_ / BM), 256, GEMM_SMEM>>>(
            curh, curl, wh + OFF_WIH + (size_t)l * G3H * H_, wl + OFF_WIH + (size_t)l * G3H * H_,
            b_ih + (size_t)l * G3H, gi, nullptr, nullptr, M_, G3H, H_);
        // 4: zero h state + barrier
        hbinit_kernel<<<32, 256>>>();
        // 5: scan  <-- profiled launch
        scan_kernel<<<NBLK * GROUPS, NTHR, SCAN_SMEM>>>(
            gi, w_hh + (size_t)l * G3H * H_, b_hh + (size_t)l * G3H, oth, otl);
        __nv_bfloat16* t1 = curh; curh = oth; oth = t1;
        __nv_bfloat16* t2 = curl; curl = otl; otl = t2;
    }

    // output MLP
    gemm2<1,1><<<dim3(H_ / BN, M_ / BM), 256, GEMM_SMEM>>>(
        curh, curl, wh + OFF_WO1, wl + OFF_WO1, b_o1, nullptr, oth, otl, M_, H_, H_);
    gemm2<0,0><<<dim3(H_ / BN, M_ / BM), 256, GEMM_SMEM>>>(
        oth, otl, wh + OFF_WO2, wl + OFF_WO2, b_o2, out, nullptr, nullptr, M_, H_, H_);
}

// round 12
// speedup vs baseline: 1.0736x; 1.0736x over previous
#include <cstdint>
#include <cuda_runtime.h>
#include <cuda_bf16.h>
#include <mma.h>

using namespace nvcuda;

// Problem dims
#define B_   64
#define T_   1024
#define H_   512
#define M_   (B_ * T_)      // 65536 rows
#define L_   4
#define G3H  (3 * H_)       // 1536

// ---------------- static device scratch (no runtime allocation) ----------------
__device__ float g_hA[(size_t)M_ * H_];          // 134 MB
__device__ float g_hB[(size_t)M_ * H_];          // 134 MB
__device__ float g_gi[(size_t)M_ * G3H];         // 402 MB
__device__ float g_hbuf[2 * B_ * H_];            // double-buffered hidden state
__device__ int   g_bar[4 * 32];                  // per-group barrier counters, 128B apart

// ---------------- helpers ----------------
__device__ __forceinline__ void split_bf16(float v, __nv_bfloat16& hi, __nv_bfloat16& lo) {
    hi = __float2bfloat16(v);
    lo = __float2bfloat16(v - __bfloat162float(hi));
}

__device__ __forceinline__ float fast_sigmoid(float x) {
    return __fdividef(1.0f, 1.0f + __expf(-x));
}
__device__ __forceinline__ float fast_tanh(float x) {
    float e = __expf(-2.0f * x);
    return __fdividef(1.0f - e, 1.0f + e);
}

// =================================================================================
// hbinit: zero hidden-state double buffer + barrier counters (replaces memsets so
// the scan lands in ncu's captured slot = 4th kernel launch)
// =================================================================================
__global__ __launch_bounds__(256)
void hbinit_kernel()
{
    int i = blockIdx.x * 256 + threadIdx.x;
    if (i < (2 * B_ * H_) / 4)          // 65536 floats -> 16384 float4
        ((float4*)g_hbuf)[i] = make_float4(0.f, 0.f, 0.f, 0.f);
    if (blockIdx.x == 0 && threadIdx.x < 4 * 32)
        g_bar[threadIdx.x] = 0;
}

// =================================================================================
// GEMM (identical to R6): C[M,N] = act(A[M,K] @ W[N,K]^T + bias[N])
// bf16x2 split (3 MMA passes). Block 128x128x32, 8 warps, warp 64x32.
// =================================================================================
#define BM 128
#define BN 128
#define BK 32
#define GLD 40

template<int RELU>
__global__ __launch_bounds__(256)
void gemm_kernel(const float* __restrict__ A, const float* __restrict__ W,
                 const float* __restrict__ bias, float* __restrict__ C,
                 int M, int N, int K)
{
    __shared__ __nv_bfloat16 sAh[BM * GLD];
    __shared__ __nv_bfloat16 sAl[BM * GLD];
    __shared__ __nv_bfloat16 sBh[BN * GLD];
    __shared__ __nv_bfloat16 sBl[BN * GLD];

    const int tid  = threadIdx.x;
    const int m0   = blockIdx.y * BM;
    const int n0   = blockIdx.x * BN;
    const int w    = tid >> 5;
    const int lane = tid & 31;
    const int wm   = w >> 2;
    const int wn   = w & 3;

    wmma::fragment<wmma::accumulator, 16, 16, 16, float> acc[4][2];
    #pragma unroll
    for (int i = 0; i < 4; i++)
        #pragma unroll
        for (int j = 0; j < 2; j++)
            wmma::fill_fragment(acc[i][j], 0.0f);

    const int r0 = tid >> 3;
    const int c4 = (tid & 7) * 4;

    for (int k0 = 0; k0 < K; k0 += BK) {
        #pragma unroll
        for (int rr = 0; rr < 4; rr++) {
            int r = r0 + rr * 32;
            float4 va = *(const float4*)&A[(size_t)(m0 + r) * K + k0 + c4];
            float4 vb = *(const float4*)&W[(size_t)(n0 + r) * K + k0 + c4];
            __nv_bfloat16 h, l;
            int base = r * GLD + c4;
            split_bf16(va.x, h, l); sAh[base + 0] = h; sAl[base + 0] = l;
            split_bf16(va.y, h, l); sAh[base + 1] = h; sAl[base + 1] = l;
            split_bf16(va.z, h, l); sAh[base + 2] = h; sAl[base + 2] = l;
            split_bf16(va.w, h, l); sAh[base + 3] = h; sAl[base + 3] = l;
            split_bf16(vb.x, h, l); sBh[base + 0] = h; sBl[base + 0] = l;
            split_bf16(vb.y, h, l); sBh[base + 1] = h; sBl[base + 1] = l;
            split_bf16(vb.z, h, l); sBh[base + 2] = h; sBl[base + 2] = l;
            split_bf16(vb.w, h, l); sBh[base + 3] = h; sBl[base + 3] = l;
        }
        __syncthreads();

        #pragma unroll
        for (int kk = 0; kk < BK; kk += 16) {
            wmma::fragment<wmma::matrix_b, 16, 16, 16, __nv_bfloat16, wmma::col_major> bh[2], bl[2];
            #pragma unroll
            for (int nf = 0; nf < 2; nf++) {
                wmma::load_matrix_sync(bh[nf], &sBh[(wn * 32 + nf * 16) * GLD + kk], GLD);
                wmma::load_matrix_sync(bl[nf], &sBl[(wn * 32 + nf * 16) * GLD + kk], GLD);
            }
            #pragma unroll
            for (int mf = 0; mf < 4; mf++) {
                wmma::fragment<wmma::matrix_a, 16, 16, 16, __nv_bfloat16, wmma::row_major> ah, al;
                wmma::load_matrix_sync(ah, &sAh[(wm * 64 + mf * 16) * GLD + kk], GLD);
                wmma::load_matrix_sync(al, &sAl[(wm * 64 + mf * 16) * GLD + kk], GLD);
                #pragma unroll
                for (int nf = 0; nf < 2; nf++) {
                    wmma::mma_sync(acc[mf][nf], ah, bh[nf], acc[mf][nf]);
                    wmma::mma_sync(acc[mf][nf], ah, bl[nf], acc[mf][nf]);
                    wmma::mma_sync(acc[mf][nf], al, bh[nf], acc[mf][nf]);
                }
            }
        }
        __syncthreads();
    }

    float* scr   = (float*)sAh;
    float* myscr = scr + w * 320;
    #pragma unroll
    for (int mf = 0; mf < 4; mf++) {
        #pragma unroll
        for (int nf = 0; nf < 2; nf++) {
            wmma::store_matrix_sync(myscr, acc[mf][nf], 20, wmma::mem_row_major);
            __syncwarp();
            #pragma unroll
            for (int e = 0; e < 8; e++) {
                int idx = e * 32 + lane;
                int r = idx >> 4, c = idx & 15;
                int row = m0 + wm * 64 + mf * 16 + r;
                int col = n0 + wn * 32 + nf * 16 + c;
                float v = myscr[r * 20 + c] + __ldg(&bias[col]);
                if (RELU) v = fmaxf(v, 0.0f);
                C[(size_t)row * N + col] = v;
            }
            __syncwarp();
        }
    }
}

// =================================================================================
// Persistent GRU scan (identical to R6 — best measured):
//  - register-resident weight fragments; tight ld.acquire spin; 1-deep gi prefetch
//  - 128 CTAs = 4 batch-groups x 32 col-CTAs; 384 thr = 3 gates x 4 K-quarters
// =================================================================================
#define SW        520
#define NBLK      32
#define GROUPS    4
#define BG        16
#define NTHR      384
#define SCAN_SMEM 50048

typedef wmma::fragment<wmma::matrix_b, 16, 16, 16, __nv_bfloat16, wmma::col_major> bfrag_t;
typedef wmma::fragment<wmma::matrix_a, 16, 16, 16, __nv_bfloat16, wmma::row_major> afrag_t;

__global__ __launch_bounds__(NTHR)
void scan_kernel(const float* __restrict__ gi, const float* __restrict__ whh,
                 const float* __restrict__ bhh, float* __restrict__ ys)
{
    extern __shared__ char smem_raw[];
    __nv_bfloat16* wtmp = (__nv_bfloat16*)smem_raw;        // init alias: 48 x SW
    __nv_bfloat16* hh = (__nv_bfloat16*)smem_raw;          // steady: 16 x SW
    __nv_bfloat16* hl = hh + 16 * SW;                      // 16 x SW
    float* gh  = (float*)(hl + 16 * SW);                   // [4][16][48]
    float* sbh = gh + 4 * 768;                             // 48
    float* hof = sbh + 48;                                 // 256 exact fp32 h

    const int tid   = threadIdx.x;
    const int g     = blockIdx.x >> 5;
    const int blk   = blockIdx.x & 31;
    const int c0    = blk * 16;
    const int w     = tid >> 5;
    const int ntile = w % 3;
    const int kq    = w / 3;
    const int bbase = g * BG;
    int* bar = &g_bar[g * 32];

    // ---- init: weight fragments into registers (hi pass, lo pass) ----
    bfrag_t bhf[8], blf[8];
    for (int i = tid; i < 48 * H_; i += NTHR) {
        int rl = i >> 9, k = i & 511;
        int grow = (rl >> 4) * H_ + c0 + (rl & 15);
        wtmp[rl * SW + k] = __float2bfloat16(whh[(size_t)grow * H_ + k]);
    }
    __syncthreads();
    #pragma unroll
    for (int i = 0; i < 8; i++)
        wmma::load_matrix_sync(bhf[i], wtmp + ntile * 16 * SW + kq * 128 + i * 16, SW);
    __syncthreads();
    for (int i = tid; i < 48 * H_; i += NTHR) {
        int rl = i >> 9, k = i & 511;
        int grow = (rl >> 4) * H_ + c0 + (rl & 15);
        float v = whh[(size_t)grow * H_ + k];
        wtmp[rl * SW + k] = __float2bfloat16(v - __bfloat162float(__float2bfloat16(v)));
    }
    __syncthreads();
    #pragma unroll
    for (int i = 0; i < 8; i++)
        wmma::load_matrix_sync(blf[i], wtmp + ntile * 16 * SW + kq * 128 + i * 16, SW);
    __syncthreads();
    if (tid < 48)
        sbh[tid] = bhh[(tid >> 4) * H_ + c0 + (tid & 15)];
    __syncthreads();

    // gi prefetch: thread tid<256 owns (b = tid>>4, j = tid&15)
    float p_ir = 0.f, p_iz = 0.f, p_in = 0.f;
    const float* gbase = gi + (size_t)(bbase + (tid >> 4)) * T_ * G3H + (c0 + (tid & 15));
    if (tid < 256) {
        p_ir = __ldg(gbase);
        p_iz = __ldg(gbase + H_);
        p_in = __ldg(gbase + 2 * H_);
    }

    for (int t = 0; t < T_; t++) {
        const int cur = t & 1, nxt = cur ^ 1;
        const float* hsrc = g_hbuf + cur * (B_ * H_);

        // Stage h[16 x 512] (L2) -> split bf16 smem; keep exact fp32 for owned cols
        for (int i = tid; i < BG * (H_ / 4); i += NTHR) {
            int b = i >> 7;
            int c = (i & 127) << 2;
            float4 v = __ldcg((const float4*)(hsrc + (size_t)(bbase + b) * H_ + c));
            __nv_bfloat16 hi, lo;
            int base = b * SW + c;
            split_bf16(v.x, hi, lo); hh[base + 0] = hi; hl[base + 0] = lo;
            split_bf16(v.y, hi, lo); hh[base + 1] = hi; hl[base + 1] = lo;
            split_bf16(v.z, hi, lo); hh[base + 2] = hi; hl[base + 2] = lo;
            split_bf16(v.w, hi, lo); hh[base + 3] = hi; hl[base + 3] = lo;
            if ((unsigned)(c - c0) < 16u)
                *(float4*)&hof[b * 16 + (c - c0)] = v;
        }
        __syncthreads();

        // gh partial[kq][16 x 48]: register-resident weights, 2 LDSM + 3 MMA per k-iter
        {
            wmma::fragment<wmma::accumulator, 16, 16, 16, float> acc;
            wmma::fill_fragment(acc, 0.0f);
            const int kbase = kq * 128;
            afrag_t ah, al;
            #pragma unroll
            for (int i = 0; i < 8; i++) {
                int k = kbase + i * 16;
                wmma::load_matrix_sync(ah, hh + k, SW);
                wmma::load_matrix_sync(al, hl + k, SW);
                wmma::mma_sync(acc, ah, bhf[i], acc);
                wmma::mma_sync(acc, ah, blf[i], acc);
                wmma::mma_sync(acc, al, bhf[i], acc);
            }
            wmma::store_matrix_sync(gh + kq * 768 + ntile * 16, acc, 48, wmma::mem_row_major);
        }
        __syncthreads();

        // Gate epilogue: 256 elements, one per thread (tid<256)
        if (tid < 256) {
            int b = tid >> 4, j = tid & 15;
            int c = c0 + j;
            size_t rowoff = (size_t)(bbase + b) * T_ + t;
            int o = b * 48 + j;
            float gr = gh[o]      + gh[768 + o]      + gh[1536 + o]      + gh[2304 + o]      + sbh[j];
            float gz = gh[o + 16] + gh[768 + o + 16] + gh[1536 + o + 16] + gh[2304 + o + 16] + sbh[16 + j];
            float gn = gh[o + 32] + gh[768 + o + 32] + gh[1536 + o + 32] + gh[2304 + o + 32] + sbh[32 + j];
            float ho = hof[b * 16 + j];
            float r = fast_sigmoid(p_ir + gr);
            float z = fast_sigmoid(p_iz + gz);
            float n = fast_tanh(p_in + r * gn);
            float hn = (1.0f - z) * n + z * ho;
            ys[rowoff * H_ + c] = hn;
            __stcg(g_hbuf + nxt * (B_ * H_) + (size_t)(bbase + b) * H_ + c, hn);
        }

        // Prefetch gi(t+1) — overlaps the barrier
        if (tid < 256 && t + 1 < T_) {
            const float* gp = gbase + (size_t)(t + 1) * G3H;
            p_ir = __ldg(gp);
            p_iz = __ldg(gp + H_);
            p_in = __ldg(gp + 2 * H_);
        }

        __syncthreads();   // order all h' stores before thread0's release
        if (tid == 0) {
            asm volatile("red.release.gpu.global.add.s32 [%0], 1;" :: "l"(bar) : "memory");
            const int target = NBLK * (t + 1);
            int v;
            do {
                asm volatile("ld.acquire.gpu.global.s32 %0, [%1];" : "=r"(v) : "l"(bar));
            } while (v < target);       // tight spin
        }
        __syncthreads();   // acquire propagates to all threads
    }
}

// =================================================================================
// Orchestration — per layer: gemm0, hbinit, scan.
// Kernel sequence: gemm1(1), gemm0(2), hbinit(3), scan(4) <- ncu captured slot
// =================================================================================
extern "C" void kernel_launch(void* const* d_in, const int* in_sizes, int n_in,
                              void* d_out, int out_size)
{
    const float* x    = (const float*)d_in[0];
    const float* w_in = (const float*)d_in[1];
    const float* b_in = (const float*)d_in[2];
    const float* w_ih = (const float*)d_in[3];
    const float* w_hh = (const float*)d_in[4];
    const float* b_ih = (const float*)d_in[5];
    const float* b_hh = (const float*)d_in[6];
    const float* w_o1 = (const float*)d_in[7];
    const float* b_o1 = (const float*)d_in[8];
    const float* w_o2 = (const float*)d_in[9];
    const float* b_o2 = (const float*)d_in[10];
    float* out = (float*)d_out;
    (void)in_sizes; (void)n_in; (void)out_size;

    float *hA, *hB, *gi;
    cudaGetSymbolAddress((void**)&hA, g_hA);
    cudaGetSymbolAddress((void**)&hB, g_hB);
    cudaGetSymbolAddress((void**)&gi, g_gi);

    cudaFuncSetAttribute(scan_kernel, cudaFuncAttributeMaxDynamicSharedMemorySize, SCAN_SMEM);

    dim3 blk(256);

    // 1: input Linear + ReLU
    gemm_kernel<1><<<dim3(H_ / BN, M_ / BM), blk>>>(x, w_in, b_in, hA, M_, H_, H_);

    float* hcur = hA;
    float* hnxt = hB;
    for (int l = 0; l < L_; l++) {
        // 2: gi = h @ w_ih^T + b_ih
        gemm_kernel<0><<<dim3(G3H / BN, M_ / BM), blk>>>(
            hcur, w_ih + (size_t)l * G3H * H_, b_ih + (size_t)l * G3H, gi, M_, G3H, H_);
        // 3: zero h double-buffer + barrier counters
        hbinit_kernel<<<64, 256>>>();
        // 4: scan  <-- ncu captured slot (layer 0)
        scan_kernel<<<NBLK * GROUPS, NTHR, SCAN_SMEM>>>(
            gi, w_hh + (size_t)l * G3H * H_, b_hh + (size_t)l * G3H, hnxt);
        float* tmp = hcur; hcur = hnxt; hnxt = tmp;
    }

    // output MLP: Linear+ReLU, then final Linear -> out
    gemm_kernel<1><<<dim3(H_ / BN, M_ / BM), blk>>>(hcur, w_o1, b_o1, hnxt, M_, H_, H_);
    gemm_kernel<0><<<dim3(H_ / BN, M_ / BM), blk>>>(hnxt, w_o2, b_o2, out, M_, H_, H_);
}

// round 13
// speedup vs baseline: 1.2636x; 1.1770x over previous
#include <cstdint>
#include <cuda_runtime.h>
#include <cuda_bf16.h>
#include <mma.h>

using namespace nvcuda;

// Problem dims
#define B_   64
#define T_   1024
#define H_   512
#define M_   (B_ * T_)      // 65536 rows
#define L_   4
#define G3H  (3 * H_)       // 1536

// ---------------- static device scratch (no runtime allocation) ----------------
__device__ float        g_hA[(size_t)M_ * H_];            // input-proj h / final ys (fp32)
__device__ float        g_hB[(size_t)M_ * H_];            // MLP intermediate
__device__ float        g_gi[(size_t)M_ * G3H];           // layer-0 gi (402 MB)
__device__ unsigned int g_ys[(size_t)L_ * T_ * B_ * H_];  // packed (hi,lo) ys per layer (536 MB)
__device__ int          g_cnt[L_ * 32];                   // per-layer counters, 128B apart

// ---------------- helpers ----------------
__device__ __forceinline__ void split_bf16(float v, __nv_bfloat16& hi, __nv_bfloat16& lo) {
    hi = __float2bfloat16(v);
    lo = __float2bfloat16(v - __bfloat162float(hi));
}
__device__ __forceinline__ float fast_sigmoid(float x) {
    return __fdividef(1.0f, 1.0f + __expf(-x));
}
__device__ __forceinline__ float fast_tanh(float x) {
    float e = __expf(-2.0f * x);
    return __fdividef(1.0f - e, 1.0f + e);
}
__device__ __forceinline__ float unpack_f(unsigned int p) {
    return __bfloat162float(__ushort_as_bfloat16((unsigned short)(p & 0xFFFF))) +
           __bfloat162float(__ushort_as_bfloat16((unsigned short)(p >> 16)));
}

// =================================================================================
// hbinit: zero wavefront counters (keeps scan at ncu's captured 4th-launch slot)
// =================================================================================
__global__ __launch_bounds__(256)
void hbinit_kernel()
{
    if (blockIdx.x == 0 && threadIdx.x < L_ * 32)
        g_cnt[threadIdx.x] = 0;
}

// =================================================================================
// GEMM (identical to R6/R12): C[M,N] = act(A[M,K] @ W[N,K]^T + bias[N])
// =================================================================================
#define BM 128
#define BN 128
#define BK 32
#define GLD 40

template<int RELU>
__global__ __launch_bounds__(256)
void gemm_kernel(const float* __restrict__ A, const float* __restrict__ W,
                 const float* __restrict__ bias, float* __restrict__ C,
                 int M, int N, int K)
{
    __shared__ __nv_bfloat16 sAh[BM * GLD];
    __shared__ __nv_bfloat16 sAl[BM * GLD];
    __shared__ __nv_bfloat16 sBh[BN * GLD];
    __shared__ __nv_bfloat16 sBl[BN * GLD];

    const int tid  = threadIdx.x;
    const int m0   = blockIdx.y * BM;
    const int n0   = blockIdx.x * BN;
    const int w    = tid >> 5;
    const int lane = tid & 31;
    const int wm   = w >> 2;
    const int wn   = w & 3;

    wmma::fragment<wmma::accumulator, 16, 16, 16, float> acc[4][2];
    #pragma unroll
    for (int i = 0; i < 4; i++)
        #pragma unroll
        for (int j = 0; j < 2; j++)
            wmma::fill_fragment(acc[i][j], 0.0f);

    const int r0 = tid >> 3;
    const int c4 = (tid & 7) * 4;

    for (int k0 = 0; k0 < K; k0 += BK) {
        #pragma unroll
        for (int rr = 0; rr < 4; rr++) {
            int r = r0 + rr * 32;
            float4 va = *(const float4*)&A[(size_t)(m0 + r) * K + k0 + c4];
            float4 vb = *(const float4*)&W[(size_t)(n0 + r) * K + k0 + c4];
            __nv_bfloat16 h, l;
            int base = r * GLD + c4;
            split_bf16(va.x, h, l); sAh[base + 0] = h; sAl[base + 0] = l;
            split_bf16(va.y, h, l); sAh[base + 1] = h; sAl[base + 1] = l;
            split_bf16(va.z, h, l); sAh[base + 2] = h; sAl[base + 2] = l;
            split_bf16(va.w, h, l); sAh[base + 3] = h; sAl[base + 3] = l;
            split_bf16(vb.x, h, l); sBh[base + 0] = h; sBl[base + 0] = l;
            split_bf16(vb.y, h, l); sBh[base + 1] = h; sBl[base + 1] = l;
            split_bf16(vb.z, h, l); sBh[base + 2] = h; sBl[base + 2] = l;
            split_bf16(vb.w, h, l); sBh[base + 3] = h; sBl[base + 3] = l;
        }
        __syncthreads();

        #pragma unroll
        for (int kk = 0; kk < BK; kk += 16) {
            wmma::fragment<wmma::matrix_b, 16, 16, 16, __nv_bfloat16, wmma::col_major> bh[2], bl[2];
            #pragma unroll
            for (int nf = 0; nf < 2; nf++) {
                wmma::load_matrix_sync(bh[nf], &sBh[(wn * 32 + nf * 16) * GLD + kk], GLD);
                wmma::load_matrix_sync(bl[nf], &sBl[(wn * 32 + nf * 16) * GLD + kk], GLD);
            }
            #pragma unroll
            for (int mf = 0; mf < 4; mf++) {
                wmma::fragment<wmma::matrix_a, 16, 16, 16, __nv_bfloat16, wmma::row_major> ah, al;
                wmma::load_matrix_sync(ah, &sAh[(wm * 64 + mf * 16) * GLD + kk], GLD);
                wmma::load_matrix_sync(al, &sAl[(wm * 64 + mf * 16) * GLD + kk], GLD);
                #pragma unroll
                for (int nf = 0; nf < 2; nf++) {
                    wmma::mma_sync(acc[mf][nf], ah, bh[nf], acc[mf][nf]);
                    wmma::mma_sync(acc[mf][nf], ah, bl[nf], acc[mf][nf]);
                    wmma::mma_sync(acc[mf][nf], al, bh[nf], acc[mf][nf]);
                }
            }
        }
        __syncthreads();
    }

    float* scr   = (float*)sAh;
    float* myscr = scr + w * 320;
    #pragma unroll
    for (int mf = 0; mf < 4; mf++) {
        #pragma unroll
        for (int nf = 0; nf < 2; nf++) {
            wmma::store_matrix_sync(myscr, acc[mf][nf], 20, wmma::mem_row_major);
            __syncwarp();
            #pragma unroll
            for (int e = 0; e < 8; e++) {
                int idx = e * 32 + lane;
                int r = idx >> 4, c = idx & 15;
                int row = m0 + wm * 64 + mf * 16 + r;
                int col = n0 + wn * 32 + nf * 16 + c;
                float v = myscr[r * 20 + c] + __ldg(&bias[col]);
                if (RELU) v = fmaxf(v, 0.0f);
                C[(size_t)row * N + col] = v;
            }
            __syncwarp();
        }
    }
}

// =================================================================================
// WAVEFRONT GRU scan: all 4 layers in ONE persistent kernel.
//  - 128 CTAs = 4 layers x 32 col-CTAs; CTA = 16 hidden cols x ALL 64 batch rows
//  - layer l at step t waits cnt[l] >= 32t (own h) and cnt[l-1] >= 32(t+1) (input)
//  - critical path: 1027 ticks instead of 4096 barrier-steps
//  - layers 1-3 compute gi on the fly (ys_prev @ w_ih slice, smem pair weights)
//  - whh slice in register fragments; M processed as 2 halves of 32 rows
//  - r,z gates: gi-MMA accumulates INTO the gh accumulator (i+h fused)
// =================================================================================
#define SW      520
#define NBLK    32
#define NTHR    384
// smem offsets (bytes)
#define OFF_HH    0                         // 32 x SW bf16  (33280)
#define OFF_HL    33280
#define OFF_WIHH  66560                     // 48 x SW bf16  (49920)
#define OFF_WIHL  116480
#define OFF_P     166400                    // [4][32][64] fp32 (32768)
#define OFF_SBH   199168                    // 48 fp32
#define OFF_SBI   199360                    // 48 fp32
#define OFF_HOF   199552                    // 32x16 fp32 (2048)
#define SCAN_SMEM 201600

typedef wmma::fragment<wmma::matrix_b, 16, 16, 16, __nv_bfloat16, wmma::col_major> bfrag_t;
typedef wmma::fragment<wmma::matrix_a, 16, 16, 16, __nv_bfloat16, wmma::row_major> afrag_t;
typedef wmma::fragment<wmma::accumulator, 16, 16, 16, float> cfrag_t;

__global__ __launch_bounds__(NTHR)
void scan_wave(const float* __restrict__ gi0, const float* __restrict__ w_ih,
               const float* __restrict__ w_hh, const float* __restrict__ b_ih,
               const float* __restrict__ b_hh, float* __restrict__ ysout)
{
    extern __shared__ char smem[];
    __nv_bfloat16* hh   = (__nv_bfloat16*)(smem + OFF_HH);
    __nv_bfloat16* hl   = (__nv_bfloat16*)(smem + OFF_HL);
    __nv_bfloat16* wihh = (__nv_bfloat16*)(smem + OFF_WIHH);
    __nv_bfloat16* wihl = (__nv_bfloat16*)(smem + OFF_WIHL);
    float* P   = (float*)(smem + OFF_P);
    float* sbh = (float*)(smem + OFF_SBH);
    float* sbi = (float*)(smem + OFF_SBI);
    float* hof = (float*)(smem + OFF_HOF);

    const int tid   = threadIdx.x;
    const int layer = blockIdx.x >> 5;
    const int blk   = blockIdx.x & 31;
    const int c0    = blk * 16;
    const int w     = tid >> 5;
    const int ntile = w % 3;       // gate r/z/n
    const int kq    = w / 3;       // K quarter (128)
    int* mycnt   = &g_cnt[layer * 32];
    int* prevcnt = &g_cnt[(layer > 0 ? layer - 1 : 0) * 32];

    const float* whh_l = w_hh + (size_t)layer * G3H * H_;
    const float* wih_l = w_ih + (size_t)layer * G3H * H_;

    // ---- init: whh slice -> register fragments (use wihh region as temp) ----
    bfrag_t bhf[8], blf[8];
    {
        __nv_bfloat16* wtmp = wihh;
        for (int i = tid; i < 48 * H_; i += NTHR) {
            int rl = i >> 9, k = i & 511;
            int grow = (rl >> 4) * H_ + c0 + (rl & 15);
            wtmp[rl * SW + k] = __float2bfloat16(whh_l[(size_t)grow * H_ + k]);
        }
        __syncthreads();
        #pragma unroll
        for (int i = 0; i < 8; i++)
            wmma::load_matrix_sync(bhf[i], wtmp + ntile * 16 * SW + kq * 128 + i * 16, SW);
        __syncthreads();
        for (int i = tid; i < 48 * H_; i += NTHR) {
            int rl = i >> 9, k = i & 511;
            int grow = (rl >> 4) * H_ + c0 + (rl & 15);
            float v = whh_l[(size_t)grow * H_ + k];
            wtmp[rl * SW + k] = __float2bfloat16(v - __bfloat162float(__float2bfloat16(v)));
        }
        __syncthreads();
        #pragma unroll
        for (int i = 0; i < 8; i++)
            wmma::load_matrix_sync(blf[i], wtmp + ntile * 16 * SW + kq * 128 + i * 16, SW);
        __syncthreads();
    }
    // ---- wih slice pair into smem (layers >= 1) ----
    if (layer > 0) {
        for (int i = tid; i < 48 * H_; i += NTHR) {
            int rl = i >> 9, k = i & 511;
            int grow = (rl >> 4) * H_ + c0 + (rl & 15);
            float v = wih_l[(size_t)grow * H_ + k];
            __nv_bfloat16 hi, lo; split_bf16(v, hi, lo);
            wihh[rl * SW + k] = hi;
            wihl[rl * SW + k] = lo;
        }
    }
    if (tid < 48) {
        int grow = (tid >> 4) * H_ + c0 + (tid & 15);
        sbh[tid] = b_hh[(size_t)layer * G3H + grow];
        sbi[tid] = b_ih[(size_t)layer * G3H + grow];
    }
    __syncthreads();

    for (int t = 0; t < T_; t++) {
        // ---- wait: own h(t-1) complete; input ys(layer-1, t) complete ----
        if (tid == 0) {
            int v;
            const int tgt0 = NBLK * t;
            do { asm volatile("ld.acquire.gpu.global.s32 %0, [%1];" : "=r"(v) : "l"(mycnt)); } while (v < tgt0);
            if (layer > 0) {
                const int tgt1 = NBLK * (t + 1);
                do { asm volatile("ld.acquire.gpu.global.s32 %0, [%1];" : "=r"(v) : "l"(prevcnt)); } while (v < tgt1);
            }
        }
        __syncthreads();

        for (int half = 0; half < 2; half++) {
            const int rowbase = half * 32;

            // ---- stage A: own ys[layer][t-1] rows rowbase..+32 (zeros at t==0) ----
            if (t == 0) {
                for (int i = tid; i < 32 * SW / 4; i += NTHR)
                    ((uint2*)hh)[i] = make_uint2(0u, 0u);
                for (int i = tid; i < 32 * SW / 4; i += NTHR)
                    ((uint2*)hl)[i] = make_uint2(0u, 0u);
                for (int i = tid; i < 512; i += NTHR)
                    hof[i] = 0.0f;
            } else {
                const unsigned int* src = g_ys + (((size_t)layer * T_ + (t - 1)) * B_ + rowbase) * H_;
                for (int i = tid; i < 4096; i += NTHR) {
                    int row = i >> 7;
                    int cc  = (i & 127) * 4;
                    uint4 v = __ldcg((const uint4*)(src + (size_t)row * H_ + cc));
                    unsigned int h01 = __byte_perm(v.x, v.y, 0x5410);
                    unsigned int l01 = __byte_perm(v.x, v.y, 0x7632);
                    unsigned int h23 = __byte_perm(v.z, v.w, 0x5410);
                    unsigned int l23 = __byte_perm(v.z, v.w, 0x7632);
                    *(uint2*)&hh[row * SW + cc] = make_uint2(h01, h23);
                    *(uint2*)&hl[row * SW + cc] = make_uint2(l01, l23);
                    if ((unsigned)(cc - c0) < 16u) {
                        int jb = cc - c0;
                        hof[row * 16 + jb + 0] = unpack_f(v.x);
                        hof[row * 16 + jb + 1] = unpack_f(v.y);
                        hof[row * 16 + jb + 2] = unpack_f(v.z);
                        hof[row * 16 + jb + 3] = unpack_f(v.w);
                    }
                }
            }
            __syncthreads();

            // ---- gh MMA (register-resident whh) ----
            cfrag_t accs[2];
            wmma::fill_fragment(accs[0], 0.0f);
            wmma::fill_fragment(accs[1], 0.0f);
            const int kb = kq * 128;
            #pragma unroll
            for (int m = 0; m < 2; m++) {
                #pragma unroll
                for (int i = 0; i < 8; i++) {
                    afrag_t ah, al;
                    wmma::load_matrix_sync(ah, hh + (m * 16) * SW + kb + i * 16, SW);
                    wmma::load_matrix_sync(al, hl + (m * 16) * SW + kb + i * 16, SW);
                    wmma::mma_sync(accs[m], ah, bhf[i], accs[m]);
                    wmma::mma_sync(accs[m], ah, blf[i], accs[m]);
                    wmma::mma_sync(accs[m], al, bhf[i], accs[m]);
                }
            }
            if (ntile == 2) {   // n gate: store h_n now, reset for i_n
                #pragma unroll
                for (int m = 0; m < 2; m++) {
                    wmma::store_matrix_sync(P + kq * 2048 + m * 16 * 64 + 32, accs[m], 64, wmma::mem_row_major);
                    wmma::fill_fragment(accs[m], 0.0f);
                }
            }
            __syncthreads();   // gh reads done before stage-B overwrites buffer

            if (layer > 0) {
                // ---- stage B: input ys[layer-1][t] rows ----
                const unsigned int* src = g_ys + (((size_t)(layer - 1) * T_ + t) * B_ + rowbase) * H_;
                for (int i = tid; i < 4096; i += NTHR) {
                    int row = i >> 7;
                    int cc  = (i & 127) * 4;
                    uint4 v = __ldcg((const uint4*)(src + (size_t)row * H_ + cc));
                    unsigned int h01 = __byte_perm(v.x, v.y, 0x5410);
                    unsigned int l01 = __byte_perm(v.x, v.y, 0x7632);
                    unsigned int h23 = __byte_perm(v.z, v.w, 0x5410);
                    unsigned int l23 = __byte_perm(v.z, v.w, 0x7632);
                    *(uint2*)&hh[row * SW + cc] = make_uint2(h01, h23);
                    *(uint2*)&hl[row * SW + cc] = make_uint2(l01, l23);
                }
                __syncthreads();

                // ---- gi MMA (smem-pair wih); r,z accumulate into fused accs ----
                #pragma unroll
                for (int m = 0; m < 2; m++) {
                    #pragma unroll
                    for (int i = 0; i < 8; i++) {
                        afrag_t ah, al;
                        bfrag_t bwh, bwl;
                        wmma::load_matrix_sync(ah, hh + (m * 16) * SW + kb + i * 16, SW);
                        wmma::load_matrix_sync(al, hl + (m * 16) * SW + kb + i * 16, SW);
                        wmma::load_matrix_sync(bwh, wihh + ntile * 16 * SW + kb + i * 16, SW);
                        wmma::load_matrix_sync(bwl, wihl + ntile * 16 * SW + kb + i * 16, SW);
                        wmma::mma_sync(accs[m], ah, bwh, accs[m]);
                        wmma::mma_sync(accs[m], ah, bwl, accs[m]);
                        wmma::mma_sync(accs[m], al, bwh, accs[m]);
                    }
                }
            }

            // ---- store partials: r,z fused at cols 0/16; i_n at col 48 ----
            {
                int colb = (ntile < 2) ? ntile * 16 : 48;
                if (ntile < 2 || layer > 0) {
                    #pragma unroll
                    for (int m = 0; m < 2; m++)
                        wmma::store_matrix_sync(P + kq * 2048 + m * 16 * 64 + colb, accs[m], 64, wmma::mem_row_major);
                }
            }
            __syncthreads();

            // ---- epilogue: 512 elements (32 rows x 16 cols) ----
            for (int idx = tid; idx < 512; idx += NTHR) {
                int rr = idx >> 4, j = idx & 15;
                int b = rowbase + rr;
                float pr = 0.f, pz = 0.f, pn = 0.f, pi = 0.f;
                #pragma unroll
                for (int q = 0; q < 4; q++) {
                    int base = q * 2048 + rr * 64;
                    pr += P[base + j];
                    pz += P[base + 16 + j];
                    pn += P[base + 32 + j];
                    pi += P[base + 48 + j];
                }
                float r, z, n;
                if (layer == 0) {
                    const float* gp = gi0 + ((size_t)b * T_ + t) * G3H + (c0 + j);
                    float ir = __ldg(gp), iz = __ldg(gp + H_), in = __ldg(gp + 2 * H_);
                    r = fast_sigmoid(ir + pr + sbh[j]);
                    z = fast_sigmoid(iz + pz + sbh[16 + j]);
                    n = fast_tanh(in + r * (pn + sbh[32 + j]));
                } else {
                    r = fast_sigmoid(pr + sbh[j] + sbi[j]);
                    z = fast_sigmoid(pz + sbh[16 + j] + sbi[16 + j]);
                    n = fast_tanh(pi + sbi[32 + j] + r * (pn + sbh[32 + j]));
                }
                float ho = hof[rr * 16 + j];
                float hn = (1.0f - z) * n + z * ho;
                __nv_bfloat16 hi, lo; split_bf16(hn, hi, lo);
                unsigned int packed = ((unsigned int)__bfloat16_as_ushort(hi)) |
                                      ((unsigned int)__bfloat16_as_ushort(lo) << 16);
                __stcg(&g_ys[(((size_t)layer * T_ + t) * B_ + b) * H_ + c0 + j], packed);
                if (layer == 3)
                    ysout[((size_t)b * T_ + t) * H_ + c0 + j] = hn;
            }
            __syncthreads();
        }   // halves

        // ---- arrive: release this tick's ys writes ----
        if (tid == 0)
            asm volatile("red.release.gpu.global.add.s32 [%0], 1;" :: "l"(mycnt) : "memory");
    }
}

// =================================================================================
// Orchestration — kernel sequence: gemm1(1), gemm0(2), hbinit(3), scan(4 <- ncu)
// =================================================================================
extern "C" void kernel_launch(void* const* d_in, const int* in_sizes, int n_in,
                              void* d_out, int out_size)
{
    const float* x    = (const float*)d_in[0];
    const float* w_in = (const float*)d_in[1];
    const float* b_in = (const float*)d_in[2];
    const float* w_ih = (const float*)d_in[3];
    const float* w_hh = (const float*)d_in[4];
    const float* b_ih = (const float*)d_in[5];
    const float* b_hh = (const float*)d_in[6];
    const float* w_o1 = (const float*)d_in[7];
    const float* b_o1 = (const float*)d_in[8];
    const float* w_o2 = (const float*)d_in[9];
    const float* b_o2 = (const float*)d_in[10];
    float* out = (float*)d_out;
    (void)in_sizes; (void)n_in; (void)out_size;

    float *hA, *hB, *gi;
    cudaGetSymbolAddress((void**)&hA, g_hA);
    cudaGetSymbolAddress((void**)&hB, g_hB);
    cudaGetSymbolAddress((void**)&gi, g_gi);

    cudaFuncSetAttribute(scan_wave, cudaFuncAttributeMaxDynamicSharedMemorySize, SCAN_SMEM);

    dim3 blk(256);

    // 1: input Linear + ReLU -> hA
    gemm_kernel<1><<<dim3(H_ / BN, M_ / BM), blk>>>(x, w_in, b_in, hA, M_, H_, H_);
    // 2: layer-0 gi (bias b_ih[0] folded)
    gemm_kernel<0><<<dim3(G3H / BN, M_ / BM), blk>>>(
        hA, w_ih, b_ih, gi, M_, G3H, H_);
    // 3: zero wavefront counters
    hbinit_kernel<<<1, 256>>>();
    // 4: the whole 4-layer wavefront recurrence (ncu captured slot)
    //    NOTE: layer 0 epilogue reads gi (which already includes b_ih[0]); the
    //    kernel's sbi for layer 0 is unused in that path.
    scan_wave<<<NBLK * L_, NTHR, SCAN_SMEM>>>(gi, w_ih, w_hh, b_ih, b_hh, hA);
    // 5/6: output MLP
    gemm_kernel<1><<<dim3(H_ / BN, M_ / BM), blk>>>(hA, w_o1, b_o1, hB, M_, H_, H_);
    gemm_kernel<0><<<dim3(H_ / BN, M_ / BM), blk>>>(hB, w_o2, b_o2, out, M_, H_, H_);
}